// round 5
// baseline (speedup 1.0000x reference)
#include <cuda_runtime.h>

// MaxPool 2x2 stride 2, (16,64,512,512) fp32 -> (16,64,256,256) fp32.
// DRAM-roofline streaming kernel (R1 layout, best measured: 91.9% of HBM spec).
// One thread -> one float4 output (4 pooled values) from 4x LDG.128 and one
// STG.128. Stores use evict-first (__stcs): output is written once and never
// re-read, so dead dirty lines shouldn't displace the read stream in L2.

#define IN_H 512
#define OUT_H 256
#define BC (16 * 64)

#define IN_ROW_F4 128   // 512 floats / 4
#define OUT_ROW_F4 64   // 256 floats / 4

__global__ void maxpool2x2_kernel(const float4* __restrict__ in4,
                                  float4* __restrict__ out4) {
    unsigned tid = blockIdx.x * blockDim.x + threadIdx.x;

    unsigned ox4  = tid & (OUT_ROW_F4 - 1);         // [0, 64)
    unsigned rest = tid >> 6;
    unsigned oy   = rest & (OUT_H - 1);             // [0, 256)
    unsigned bc   = rest >> 8;                      // [0, 1024)

    unsigned ibase = bc * (IN_H * IN_ROW_F4) + (oy * 2) * IN_ROW_F4 + ox4 * 2;

    float4 r0a = in4[ibase];
    float4 r0b = in4[ibase + 1];
    float4 r1a = in4[ibase + IN_ROW_F4];
    float4 r1b = in4[ibase + IN_ROW_F4 + 1];

    float4 o;
    o.x = fmaxf(fmaxf(r0a.x, r0a.y), fmaxf(r1a.x, r1a.y));
    o.y = fmaxf(fmaxf(r0a.z, r0a.w), fmaxf(r1a.z, r1a.w));
    o.z = fmaxf(fmaxf(r0b.x, r0b.y), fmaxf(r1b.x, r1b.y));
    o.w = fmaxf(fmaxf(r0b.z, r0b.w), fmaxf(r1b.z, r1b.w));

    __stcs(&out4[tid], o);
}

extern "C" void kernel_launch(void* const* d_in, const int* in_sizes, int n_in,
                              void* d_out, int out_size) {
    const float4* in4 = (const float4*)d_in[0];
    float4* out4 = (float4*)d_out;

    const unsigned total = (unsigned)BC * OUT_H * OUT_ROW_F4;  // 16,777,216
    const int threads = 256;
    const unsigned blocks = total / threads;                   // 65,536

    maxpool2x2_kernel<<<blocks, threads>>>(in4, out4);
}

// round 6
// speedup vs baseline: 1.0026x; 1.0026x over previous
#include <cuda_runtime.h>

// MaxPool 2x2 stride 2, (16,64,512,512) fp32 -> (16,64,256,256) fp32.
// FINAL: DRAM-roofline streaming kernel at the measured mixed-stream HBM
// ceiling (91.9% of 8TB/s spec, 7283 GB/s). One thread -> one float4 output
// (4 pooled values) from 4x coalesced LDG.128 and one STG.128.
//
// Plateau evidence (5 variants, all 88-92% of spec): per-thread f4 (this one,
// best), 64B/thread spread (worse: wavefront inflation), perfect-coalesce f2
// out, perfect-coalesce MLP=8, and __stcs store variants (all neutral).
// SM-side metrics are idle (issue 7%, L1 41%, occ 79%) -> DRAM interface bound.

#define IN_H 512
#define OUT_H 256
#define BC (16 * 64)

#define IN_ROW_F4 128   // 512 floats / 4
#define OUT_ROW_F4 64   // 256 floats / 4

__global__ void maxpool2x2_kernel(const float4* __restrict__ in4,
                                  float4* __restrict__ out4) {
    unsigned tid = blockIdx.x * blockDim.x + threadIdx.x;

    unsigned ox4  = tid & (OUT_ROW_F4 - 1);         // [0, 64)
    unsigned rest = tid >> 6;
    unsigned oy   = rest & (OUT_H - 1);             // [0, 256)
    unsigned bc   = rest >> 8;                      // [0, 1024)

    unsigned ibase = bc * (IN_H * IN_ROW_F4) + (oy * 2) * IN_ROW_F4 + ox4 * 2;

    float4 r0a = in4[ibase];
    float4 r0b = in4[ibase + 1];
    float4 r1a = in4[ibase + IN_ROW_F4];
    float4 r1b = in4[ibase + IN_ROW_F4 + 1];

    float4 o;
    o.x = fmaxf(fmaxf(r0a.x, r0a.y), fmaxf(r1a.x, r1a.y));
    o.y = fmaxf(fmaxf(r0a.z, r0a.w), fmaxf(r1a.z, r1a.w));
    o.z = fmaxf(fmaxf(r0b.x, r0b.y), fmaxf(r1b.x, r1b.y));
    o.w = fmaxf(fmaxf(r0b.z, r0b.w), fmaxf(r1b.z, r1b.w));

    out4[tid] = o;
}

extern "C" void kernel_launch(void* const* d_in, const int* in_sizes, int n_in,
                              void* d_out, int out_size) {
    const float4* in4 = (const float4*)d_in[0];
    float4* out4 = (float4*)d_out;

    const unsigned total = (unsigned)BC * OUT_H * OUT_ROW_F4;  // 16,777,216
    const int threads = 256;
    const unsigned blocks = total / threads;                   // 65,536

    maxpool2x2_kernel<<<blocks, threads>>>(in4, out4);
}